// round 8
// baseline (speedup 1.0000x reference)
#include <cuda_runtime.h>
#include <cuda_bf16.h>
#include <stdint.h>

#define N_POINTS  1048576
#define DD        64
#define NUM_BINS  (DD*DD*DD)         // 262144
#define LL        128
#define TT        8
#define CAP       8
#define STORE_CAP 32

#define LAT_ELEMS  (LL*LL*LL*TT)     // 16777216
#define BUF_ELEMS  (NUM_BINS*CAP*3)
#define PLANE      (LL*LL*LL)        // 2097152 floats per type-plane
#define XSLICE     (LL*LL)           // 16384 floats per x-slice
#define QROW       (LL*2)            // 256: stride of (y>>1) in morton plane

// grids
#define BIN_BLOCKS    (N_POINTS/256)           // 4096
#define SPLAT_BLOCKS  (NUM_BINS/8/8)           // 4096 (8 bins/warp, 8 warps/block)
#define TR_BLOCKS     (PLANE/4/256)            // 2048 (one thread per 2x2 (y,z) quad)
#define FILL_BLOCKS   (NUM_BINS/256)           // 1024
#define C_BLOCKS      (TR_BLOCKS + FILL_BLOCKS) // 3072, groups of 3

// Persistent state. Zero-initialized at module load; every invocation
// re-zeroes what it consumed (self-cleaning -> graph-replay deterministic).
__device__ int    g_count[NUM_BINS];
__device__ __align__(16)  float4 g_pts[NUM_BINS * STORE_CAP]; // (x,y,z,(idx<<3)|t)
__device__ __align__(128) float  g_scr[TT * PLANE];  // [t][x][morton(y,z)]

// morton(y,z) 2x2 packing inside each x-slice
__device__ __forceinline__ size_t midx(int t, int x, int y, int z) {
    return (size_t)t * PLANE + (size_t)x * XSLICE
         + (y >> 1) * QROW + (z >> 1) * 4 + (y & 1) * 2 + (z & 1);
}

__device__ __forceinline__ void red4(float* p, float a, float b, float c, float d) {
    asm volatile("red.global.add.v4.f32 [%0], {%1,%2,%3,%4};"
                 :: "l"(p), "f"(a), "f"(b), "f"(c), "f"(d) : "memory");
}

// ---- scalar bounds-checked splat (boundary + overflow path), morton addrs --
__device__ __forceinline__ void splat_scalar(float px, float py, float pz, int t)
{
    int cx = (int)floorf(px * 4.0f);
    int cy = (int)floorf(py * 4.0f);
    int cz = (int)floorf(pz * 4.0f);

    const float inv = 1.0f / (2.0f * 0.3f * 0.3f);
    float ex[3], ey[3], ez[3];
    #pragma unroll
    for (int o = 0; o < 3; o++) {
        float vx = px - ((float)(cx + o - 1) + 0.5f) * 0.25f;
        float vy = py - ((float)(cy + o - 1) + 0.5f) * 0.25f;
        float vz = pz - ((float)(cz + o - 1) + 0.5f) * 0.25f;
        ex[o] = __expf(-vx * vx * inv);
        ey[o] = __expf(-vy * vy * inv);
        ez[o] = __expf(-vz * vz * inv);
    }
    #pragma unroll
    for (int ix = 0; ix < 3; ix++) {
        int x = cx + ix - 1;
        if ((unsigned)x >= (unsigned)LL) continue;
        #pragma unroll
        for (int iy = 0; iy < 3; iy++) {
            int y = cy + iy - 1;
            if ((unsigned)y >= (unsigned)LL) continue;
            float exy = ex[ix] * ey[iy];
            #pragma unroll
            for (int iz = 0; iz < 3; iz++) {
                int z = cz + iz - 1;
                if ((unsigned)z >= (unsigned)LL) continue;
                atomicAdd(g_scr + midx(t, x, y, z), exy * ez[iz]);
            }
        }
    }
}

// ---- interior fast splat: 12 uniform red4 into morton quads ---------------
__device__ __forceinline__ void splat_rec(float4 r)
{
    float px = r.x, py = r.y, pz = r.z;
    int t = __float_as_int(r.w) & 7;

    int cx = (int)floorf(px * 4.0f);
    int cy = (int)floorf(py * 4.0f);
    int cz = (int)floorf(pz * 4.0f);

    bool interior = ((unsigned)(cx - 1) < (unsigned)(LL - 2)) &&
                    ((unsigned)(cy - 1) < (unsigned)(LL - 2)) &&
                    ((unsigned)(cz - 1) < (unsigned)(LL - 2));
    if (!interior) { splat_scalar(px, py, pz, t); return; }

    const float inv = 1.0f / (2.0f * 0.3f * 0.3f);
    float ex[3], ey[3], ez[3];
    #pragma unroll
    for (int o = 0; o < 3; o++) {
        float vx = px - ((float)(cx + o - 1) + 0.5f) * 0.25f;
        float vy = py - ((float)(cy + o - 1) + 0.5f) * 0.25f;
        float vz = pz - ((float)(cz + o - 1) + 0.5f) * 0.25f;
        ex[o] = __expf(-vx * vx * inv);
        ey[o] = __expf(-vy * vy * inv);
        ez[o] = __expf(-vz * vz * inv);
    }

    int ay = (cy - 1) & 1, qy0 = (cy - 1) >> 1;
    int az = (cz - 1) & 1, qz0 = (cz - 1) >> 1;

    // shifted axis vectors over the 2-quad span (4 cells)
    float vy0 = ay ? 0.f   : ey[0];
    float vy1 = ay ? ey[0] : ey[1];
    float vy2 = ay ? ey[1] : ey[2];
    float vy3 = ay ? ey[2] : 0.f;
    float vz0 = az ? 0.f   : ez[0];
    float vz1 = az ? ez[0] : ez[1];
    float vz2 = az ? ez[1] : ez[2];
    float vz3 = az ? ez[2] : 0.f;

    // outer products p[m][n] = vy[m]*vz[n]
    float p00 = vy0*vz0, p01 = vy0*vz1, p02 = vy0*vz2, p03 = vy0*vz3;
    float p10 = vy1*vz0, p11 = vy1*vz1, p12 = vy1*vz2, p13 = vy1*vz3;
    float p20 = vy2*vz0, p21 = vy2*vz1, p22 = vy2*vz2, p23 = vy2*vz3;
    float p30 = vy3*vz0, p31 = vy3*vz1, p32 = vy3*vz2, p33 = vy3*vz3;

    float* base = g_scr + (size_t)t * PLANE + (size_t)(cx - 1) * XSLICE
                + qy0 * QROW + qz0 * 4;

    #pragma unroll
    for (int ix = 0; ix < 3; ix++) {
        float w = ex[ix];
        float* bx = base + ix * XSLICE;
        // quad element order: e = (y&1)*2 + (z&1)
        red4(bx,            w*p00, w*p01, w*p10, w*p11);   // gy=0,gz=0
        red4(bx + 4,        w*p02, w*p03, w*p12, w*p13);   // gy=0,gz=1
        red4(bx + QROW,     w*p20, w*p21, w*p30, w*p31);   // gy=1,gz=0
        red4(bx + QROW + 4, w*p22, w*p23, w*p32, w*p33);   // gy=1,gz=1
    }
}

// ---------------------------------------------------------------------------
// Kernel A: bin scatter only.
// ---------------------------------------------------------------------------
__global__ void __launch_bounds__(256)
bin_kernel(const float* __restrict__ pts,
           const int* __restrict__ mask,
           const int* __restrict__ types)
{
    int i = blockIdx.x * blockDim.x + threadIdx.x;
    if (i >= N_POINTS) return;
    if (!mask[i]) return;

    float px = pts[3*i + 0];
    float py = pts[3*i + 1];
    float pz = pts[3*i + 2];
    int   t  = types[i];

    int bx = min(max((int)floorf(px * 2.0f), 0), DD - 1);
    int by = min(max((int)floorf(py * 2.0f), 0), DD - 1);
    int bz = min(max((int)floorf(pz * 2.0f), 0), DD - 1);
    int bin = (bx * DD + by) * DD + bz;
    int pos = atomicAdd(&g_count[bin], 1);
    if (pos < STORE_CAP) {
        g_pts[bin * STORE_CAP + pos] =
            make_float4(px, py, pz, __int_as_float((i << 3) | t));
    } else {
        splat_scalar(px, py, pz, t);   // P ~ 1e-22, keeps result exact
    }
}

// ---------------------------------------------------------------------------
// Kernel B: splat with warp-compaction. Each warp owns 8 consecutive bins,
// records assigned densely to lanes (avg 34 records / 32 lanes).
// ---------------------------------------------------------------------------
__global__ void __launch_bounds__(256)
splat_kernel()
{
    int wid  = (blockIdx.x * 256 + threadIdx.x) >> 5;   // global warp id
    int lane = threadIdx.x & 31;
    int B = wid * 8;                                     // first bin of warp

    int pre[9];
    pre[0] = 0;
    #pragma unroll
    for (int j = 0; j < 8; j++)
        pre[j + 1] = pre[j] + min(g_count[B + j], STORE_CAP);
    int total = pre[8];

    for (int r = lane; r < total; r += 32) {
        int j = 0;
        #pragma unroll
        for (int q = 1; q < 8; q++) j += (r >= pre[q]);
        int slot = r - pre[j];
        float4 rec = g_pts[(B + j) * STORE_CAP + slot];
        splat_rec(rec);
    }
}

// ---------------------------------------------------------------------------
// transpose + scratch zero-back: one thread per (x, qy, qz) quad.
// ---------------------------------------------------------------------------
__device__ __forceinline__ void do_transpose(int tb, float* __restrict__ lat)
{
    int idx = tb * 256 + threadIdx.x;        // [0, 524288)
    int x   = idx >> 12;
    int rem = idx & 4095;
    int qy  = rem >> 6;
    int qz  = rem & 63;

    float4 v[TT];
    size_t base = (size_t)x * XSLICE + qy * QROW + qz * 4;
    #pragma unroll
    for (int t = 0; t < TT; t++) {
        float4* p = (float4*)(g_scr + (size_t)t * PLANE + base);
        v[t] = *p;
        *p = make_float4(0.f, 0.f, 0.f, 0.f);   // self-clean for next replay
    }

    int y0 = qy * 2, z0 = qz * 2;
    // element e = (y&1)*2 + (z&1): (0,0)->x (0,1)->y (1,0)->z (1,1)->w
    {
        float4* o = (float4*)(lat + ((size_t)(x * LL + y0) * LL + z0) * TT);
        o[0] = make_float4(v[0].x, v[1].x, v[2].x, v[3].x);
        o[1] = make_float4(v[4].x, v[5].x, v[6].x, v[7].x);
        o[2] = make_float4(v[0].y, v[1].y, v[2].y, v[3].y);
        o[3] = make_float4(v[4].y, v[5].y, v[6].y, v[7].y);
    }
    {
        float4* o = (float4*)(lat + ((size_t)(x * LL + y0 + 1) * LL + z0) * TT);
        o[0] = make_float4(v[0].z, v[1].z, v[2].z, v[3].z);
        o[1] = make_float4(v[4].z, v[5].z, v[6].z, v[7].z);
        o[2] = make_float4(v[0].w, v[1].w, v[2].w, v[3].w);
        o[3] = make_float4(v[4].w, v[5].w, v[6].w, v[7].w);
    }
}

// ---------------------------------------------------------------------------
// fill + counter zero-back: one bin per thread.
// ---------------------------------------------------------------------------
__device__ __forceinline__ void do_fill(int fb,
                                        float* __restrict__ buf,
                                        float* __restrict__ bmask)
{
    int b = fb * 256 + threadIdx.x;

    const float4* rec = &g_pts[(size_t)b * STORE_CAP];

    float w8[CAP];
    #pragma unroll
    for (int e = 0; e < CAP; e++) w8[e] = rec[e].w;

    int cnt = g_count[b];
    g_count[b] = 0;                       // self-clean for next replay
    int m = min(cnt, STORE_CAP);

    int key[CAP];
    #pragma unroll
    for (int s = 0; s < CAP; s++) key[s] = 0x7FFFFFFF;

    #pragma unroll
    for (int e = 0; e < CAP; e++) {
        if (e >= m) break;
        int k = (__float_as_int(w8[e]) << 5) | e;
        #pragma unroll
        for (int j = 0; j < CAP; j++) {
            int lo = min(k, key[j]);
            int hi = max(k, key[j]);
            key[j] = lo;
            k = hi;
        }
    }
    for (int e = CAP; e < m; e++) {
        int k = (__float_as_int(rec[e].w) << 5) | e;
        #pragma unroll
        for (int j = 0; j < CAP; j++) {
            int lo = min(k, key[j]);
            int hi = max(k, key[j]);
            key[j] = lo;
            k = hi;
        }
    }

    int nval = min(cnt, CAP);
    float o[CAP * 3];
    float mk[CAP];
    #pragma unroll
    for (int s = 0; s < CAP; s++) {
        float x = 0.f, y = 0.f, z = 0.f, mv = 0.f;
        if (s < nval) {
            float4 r = rec[key[s] & (STORE_CAP - 1)];
            x = r.x; y = r.y; z = r.z; mv = 1.0f;
        }
        o[3*s + 0] = x; o[3*s + 1] = y; o[3*s + 2] = z;
        mk[s] = mv;
    }

    float4* bp = (float4*)(buf + (size_t)b * (CAP * 3));
    #pragma unroll
    for (int q = 0; q < 6; q++)
        bp[q] = make_float4(o[4*q + 0], o[4*q + 1], o[4*q + 2], o[4*q + 3]);

    float4* mp = (float4*)(bmask + (size_t)b * CAP);
    mp[0] = make_float4(mk[0], mk[1], mk[2], mk[3]);
    mp[1] = make_float4(mk[4], mk[5], mk[6], mk[7]);
}

// ---------------------------------------------------------------------------
// Kernel C: interleaved [transpose | fill]. Groups of 3: r<2 transpose, r==2 fill.
// ---------------------------------------------------------------------------
__global__ void __launch_bounds__(256)
transpose_fill_kernel(float* __restrict__ lat,
                      float* __restrict__ buf,
                      float* __restrict__ bmask)
{
    int g = blockIdx.x;
    int k = g / 3;
    int r = g - k * 3;
    if (r < 2) do_transpose(k * 2 + r, lat);
    else       do_fill(k, buf, bmask);
}

// ---------------------------------------------------------------------------
extern "C" void kernel_launch(void* const* d_in, const int* in_sizes, int n_in,
                              void* d_out, int out_size)
{
    const float* points = (const float*)d_in[0];
    const int*   mask   = (const int*)d_in[1];
    const int*   types  = (const int*)d_in[2];

    float* out   = (float*)d_out;
    float* lat   = out;                       // [128,128,128,8]
    float* buf   = out + LAT_ELEMS;           // [262144,8,3]
    float* bmask = buf + BUF_ELEMS;           // [262144,8]

    bin_kernel<<<BIN_BLOCKS, 256>>>(points, mask, types);
    splat_kernel<<<SPLAT_BLOCKS, 256>>>();
    transpose_fill_kernel<<<C_BLOCKS, 256>>>(lat, buf, bmask);
}

// round 9
// speedup vs baseline: 1.0979x; 1.0979x over previous
#include <cuda_runtime.h>
#include <cuda_bf16.h>
#include <stdint.h>

#define N_POINTS  1048576
#define DD        64
#define NUM_BINS  (DD*DD*DD)         // 262144
#define LL        128
#define TT        8
#define CAP       8
#define STORE_CAP 32

#define LAT_ELEMS  (LL*LL*LL*TT)     // 16777216
#define BUF_ELEMS  (NUM_BINS*CAP*3)
#define PLANE      (LL*LL*LL)        // 2097152 floats per type-plane
#define XSLICE     (LL*LL)           // 16384

// grids
#define BIN_BLOCKS   (N_POINTS/256)              // 4096
#define B_GROUPS     (NUM_BINS/256)              // 1024 groups of (8 splat + 1 fill)
#define B_BLOCKS     (B_GROUPS*9)                // 9216
#define TR_BLOCKS    ((PLANE/4)/256)             // 2048

// Persistent state. Zero-initialized at load; each invocation re-zeroes what
// it consumed (self-cleaning -> graph-replay deterministic, no memsets).
__device__ int    g_count[NUM_BINS];
__device__ __align__(16)  float4 g_pts[NUM_BINS * STORE_CAP]; // (x,y,z,(idx<<3)|t)
__device__ __align__(128) float  g_scr[TT * PLANE];           // [t][x][y][z]

// ---- vector reductions ------------------------------------------------------
__device__ __forceinline__ void red4(float* p, float a, float b, float c, float d) {
    asm volatile("red.global.add.v4.f32 [%0], {%1,%2,%3,%4};"
                 :: "l"(p), "f"(a), "f"(b), "f"(c), "f"(d) : "memory");
}
__device__ __forceinline__ void red2(float* p, float a, float b) {
    asm volatile("red.global.add.v2.f32 [%0], {%1,%2};"
                 :: "l"(p), "f"(a), "f"(b) : "memory");
}

// ---- scalar bounds-checked splat (boundary + overflow path) ----------------
__device__ __forceinline__ void splat_scalar(float px, float py, float pz, int t)
{
    int cx = (int)floorf(px * 4.0f);
    int cy = (int)floorf(py * 4.0f);
    int cz = (int)floorf(pz * 4.0f);

    const float inv = 1.0f / (2.0f * 0.3f * 0.3f);
    float ex[3], ey[3], ez[3];
    #pragma unroll
    for (int o = 0; o < 3; o++) {
        float vx = px - ((float)(cx + o - 1) + 0.5f) * 0.25f;
        float vy = py - ((float)(cy + o - 1) + 0.5f) * 0.25f;
        float vz = pz - ((float)(cz + o - 1) + 0.5f) * 0.25f;
        ex[o] = __expf(-vx * vx * inv);
        ey[o] = __expf(-vy * vy * inv);
        ez[o] = __expf(-vz * vz * inv);
    }
    float* pl = g_scr + (size_t)t * PLANE;
    #pragma unroll
    for (int ix = 0; ix < 3; ix++) {
        int x = cx + ix - 1;
        if ((unsigned)x >= (unsigned)LL) continue;
        #pragma unroll
        for (int iy = 0; iy < 3; iy++) {
            int y = cy + iy - 1;
            if ((unsigned)y >= (unsigned)LL) continue;
            float exy = ex[ix] * ey[iy];
            #pragma unroll
            for (int iz = 0; iz < 3; iz++) {
                int z = cz + iz - 1;
                if ((unsigned)z >= (unsigned)LL) continue;
                atomicAdd(pl + x * XSLICE + y * LL + z, exy * ez[iz]);
            }
        }
    }
}

// ---------------------------------------------------------------------------
// Kernel A: bin scatter only.
// ---------------------------------------------------------------------------
__global__ void __launch_bounds__(256)
bin_kernel(const float* __restrict__ pts,
           const int* __restrict__ mask,
           const int* __restrict__ types)
{
    int i = blockIdx.x * blockDim.x + threadIdx.x;
    if (i >= N_POINTS) return;
    if (!mask[i]) return;

    float px = pts[3*i + 0];
    float py = pts[3*i + 1];
    float pz = pts[3*i + 2];
    int   t  = types[i];

    int bx = min(max((int)floorf(px * 2.0f), 0), DD - 1);
    int by = min(max((int)floorf(py * 2.0f), 0), DD - 1);
    int bz = min(max((int)floorf(pz * 2.0f), 0), DD - 1);
    int bin = (bx * DD + by) * DD + bz;
    int pos = atomicAdd(&g_count[bin], 1);
    if (pos < STORE_CAP) {
        g_pts[bin * STORE_CAP + pos] =
            make_float4(px, py, pz, __int_as_float((i << 3) | t));
    } else {
        splat_scalar(px, py, pz, t);   // P ~ 1e-22, keeps result exact
    }
}

// ---------------------------------------------------------------------------
// splat work for one block (bin = tid/8, slot = tid%8) — R5 minimal-element
// vector-RED scheme into linear [t][x][y][z] scratch.
// ---------------------------------------------------------------------------
__device__ __forceinline__ void do_splat(int sblock)
{
    int tid = sblock * 256 + threadIdx.x;
    int bin  = tid >> 3;
    int slot = tid & 7;

    int m = min(g_count[bin], STORE_CAP);
    for (int s = slot; s < m; s += 8) {
        float4 r = g_pts[bin * STORE_CAP + s];
        float px = r.x, py = r.y, pz = r.z;
        int t = __float_as_int(r.w) & 7;

        int cx = (int)floorf(px * 4.0f);
        int cy = (int)floorf(py * 4.0f);
        int cz = (int)floorf(pz * 4.0f);

        bool interior = ((unsigned)(cx - 1) < (unsigned)(LL - 2)) &&
                        ((unsigned)(cy - 1) < (unsigned)(LL - 2)) &&
                        ((unsigned)(cz - 1) < (unsigned)(LL - 2));
        if (!interior) { splat_scalar(px, py, pz, t); continue; }

        const float inv = 1.0f / (2.0f * 0.3f * 0.3f);
        float ex[3], ey[3], ez[3];
        #pragma unroll
        for (int o = 0; o < 3; o++) {
            float vx = px - ((float)(cx + o - 1) + 0.5f) * 0.25f;
            float vy = py - ((float)(cy + o - 1) + 0.5f) * 0.25f;
            float vz = pz - ((float)(cz + o - 1) + 0.5f) * 0.25f;
            ex[o] = __expf(-vx * vx * inv);
            ey[o] = __expf(-vy * vy * inv);
            ez[o] = __expf(-vz * vz * inv);
        }

        int zb = cz - 1;
        int a  = zb & 3;
        float* p00 = g_scr + (size_t)t * PLANE
                   + (cx - 1) * XSLICE + (cy - 1) * LL + zb;

        if (a == 0) {
            #pragma unroll
            for (int ix = 0; ix < 3; ix++)
                #pragma unroll
                for (int iy = 0; iy < 3; iy++) {
                    float w = ex[ix] * ey[iy];
                    float* p = p00 + ix * XSLICE + iy * LL;
                    red4(p, w*ez[0], w*ez[1], w*ez[2], 0.0f);
                }
        } else if (a == 1) {
            #pragma unroll
            for (int ix = 0; ix < 3; ix++)
                #pragma unroll
                for (int iy = 0; iy < 3; iy++) {
                    float w = ex[ix] * ey[iy];
                    float* p = p00 + ix * XSLICE + iy * LL;
                    red4(p - 1, 0.0f, w*ez[0], w*ez[1], w*ez[2]);
                }
        } else if (a == 2) {
            #pragma unroll
            for (int ix = 0; ix < 3; ix++)
                #pragma unroll
                for (int iy = 0; iy < 3; iy++) {
                    float w = ex[ix] * ey[iy];
                    float* p = p00 + ix * XSLICE + iy * LL;
                    red2(p, w*ez[0], w*ez[1]);
                    atomicAdd(p + 2, w*ez[2]);
                }
        } else {
            #pragma unroll
            for (int ix = 0; ix < 3; ix++)
                #pragma unroll
                for (int iy = 0; iy < 3; iy++) {
                    float w = ex[ix] * ey[iy];
                    float* p = p00 + ix * XSLICE + iy * LL;
                    atomicAdd(p, w*ez[0]);
                    red2(p + 1, w*ez[1], w*ez[2]);
                }
        }
    }
}

// ---------------------------------------------------------------------------
// fill work for one block (one bin per thread). Does NOT zero g_count
// (splat blocks still reading it); kernel C zeroes counters.
// ---------------------------------------------------------------------------
__device__ __forceinline__ void do_fill(int fb,
                                        float* __restrict__ buf,
                                        float* __restrict__ bmask)
{
    int b = fb * 256 + threadIdx.x;

    const float4* rec = &g_pts[(size_t)b * STORE_CAP];

    float w8[CAP];
    #pragma unroll
    for (int e = 0; e < CAP; e++) w8[e] = rec[e].w;

    int cnt = g_count[b];
    int m = min(cnt, STORE_CAP);

    int key[CAP];
    #pragma unroll
    for (int s = 0; s < CAP; s++) key[s] = 0x7FFFFFFF;

    #pragma unroll
    for (int e = 0; e < CAP; e++) {
        if (e >= m) break;
        int k = (__float_as_int(w8[e]) << 5) | e;
        #pragma unroll
        for (int j = 0; j < CAP; j++) {
            int lo = min(k, key[j]);
            int hi = max(k, key[j]);
            key[j] = lo;
            k = hi;
        }
    }
    for (int e = CAP; e < m; e++) {
        int k = (__float_as_int(rec[e].w) << 5) | e;
        #pragma unroll
        for (int j = 0; j < CAP; j++) {
            int lo = min(k, key[j]);
            int hi = max(k, key[j]);
            key[j] = lo;
            k = hi;
        }
    }

    int nval = min(cnt, CAP);
    float o[CAP * 3];
    float mk[CAP];
    #pragma unroll
    for (int s = 0; s < CAP; s++) {
        float x = 0.f, y = 0.f, z = 0.f, mv = 0.f;
        if (s < nval) {
            float4 r = rec[key[s] & (STORE_CAP - 1)];
            x = r.x; y = r.y; z = r.z; mv = 1.0f;
        }
        o[3*s + 0] = x; o[3*s + 1] = y; o[3*s + 2] = z;
        mk[s] = mv;
    }

    float4* bp = (float4*)(buf + (size_t)b * (CAP * 3));
    #pragma unroll
    for (int q = 0; q < 6; q++)
        bp[q] = make_float4(o[4*q + 0], o[4*q + 1], o[4*q + 2], o[4*q + 3]);

    float4* mp = (float4*)(bmask + (size_t)b * CAP);
    mp[0] = make_float4(mk[0], mk[1], mk[2], mk[3]);
    mp[1] = make_float4(mk[4], mk[5], mk[6], mk[7]);
}

// ---------------------------------------------------------------------------
// Kernel B: interleaved [splat | fill]. Groups of 9: r<8 splat, r==8 fill.
// ---------------------------------------------------------------------------
__global__ void __launch_bounds__(256)
splat_fill_kernel(float* __restrict__ buf, float* __restrict__ bmask)
{
    int g = blockIdx.x;
    int k = g / 9;
    int r = g - k * 9;
    if (r < 8) do_splat(k * 8 + r);
    else       do_fill(k, buf, bmask);
}

// ---------------------------------------------------------------------------
// Kernel C: transpose [t][x][y][z] -> [x][y][z][t], zero-back scratch,
// zero counters (first NUM_BINS threads).
// ---------------------------------------------------------------------------
__global__ void __launch_bounds__(256)
transpose_kernel(float* __restrict__ lat)
{
    int idx = blockIdx.x * blockDim.x + threadIdx.x;  // [0, PLANE/4)
    if (idx < NUM_BINS) g_count[idx] = 0;             // self-clean counters

    // idx -> (x, y, z0): 4 consecutive z per thread
    int x   = idx >> 10;            // PLANE/4 = 524288 ; per x: 128*32 = 4096... 
    int rem = idx & 1023;
    // careful: per x-slice there are XSLICE/4 = 4096 float4 quads
    x   = idx >> 12;
    rem = idx & 4095;
    int y  = rem >> 5;
    int z4 = (rem & 31) * 4;

    float4 v[TT];
    size_t base = (size_t)x * XSLICE + y * LL + z4;
    #pragma unroll
    for (int t = 0; t < TT; t++) {
        float4* p = (float4*)(g_scr + (size_t)t * PLANE + base);
        v[t] = *p;
        *p = make_float4(0.f, 0.f, 0.f, 0.f);        // self-clean scratch
    }

    // write 4 cells x 8 types = 128 contiguous bytes
    float4* o = (float4*)(lat + base * TT);
    o[0] = make_float4(v[0].x, v[1].x, v[2].x, v[3].x);
    o[1] = make_float4(v[4].x, v[5].x, v[6].x, v[7].x);
    o[2] = make_float4(v[0].y, v[1].y, v[2].y, v[3].y);
    o[3] = make_float4(v[4].y, v[5].y, v[6].y, v[7].y);
    o[4] = make_float4(v[0].z, v[1].z, v[2].z, v[3].z);
    o[5] = make_float4(v[4].z, v[5].z, v[6].z, v[7].z);
    o[6] = make_float4(v[0].w, v[1].w, v[2].w, v[3].w);
    o[7] = make_float4(v[4].w, v[5].w, v[6].w, v[7].w);
}

// ---------------------------------------------------------------------------
extern "C" void kernel_launch(void* const* d_in, const int* in_sizes, int n_in,
                              void* d_out, int out_size)
{
    const float* points = (const float*)d_in[0];
    const int*   mask   = (const int*)d_in[1];
    const int*   types  = (const int*)d_in[2];

    float* out   = (float*)d_out;
    float* lat   = out;                       // [128,128,128,8]
    float* buf   = out + LAT_ELEMS;           // [262144,8,3]
    float* bmask = buf + BUF_ELEMS;           // [262144,8]

    bin_kernel<<<BIN_BLOCKS, 256>>>(points, mask, types);
    splat_fill_kernel<<<B_BLOCKS, 256>>>(buf, bmask);
    transpose_kernel<<<TR_BLOCKS, 256>>>(lat);
}

// round 10
// speedup vs baseline: 1.8146x; 1.6528x over previous
#include <cuda_runtime.h>
#include <cuda_bf16.h>
#include <stdint.h>

#define N_POINTS  1048576
#define DD        64
#define NUM_BINS  (DD*DD*DD)         // 262144
#define LL        128
#define TT        8
#define CAP       8
#define STORE_CAP 32

#define LAT_ELEMS  (LL*LL*LL*TT)     // 16777216
#define BUF_ELEMS  (NUM_BINS*CAP*3)
#define PLANE      (LL*LL*LL)        // 2097152 floats per type-plane
#define XSLICE     (LL*LL)           // 16384

// grids
#define BIN_BLOCKS   (N_POINTS/256)               // 4096
#define ZERO_BLOCKS  ((TT*PLANE/4)/256)           // 16384 (float4 stores)
#define A_BLOCKS     (BIN_BLOCKS + ZERO_BLOCKS)   // 20480, groups of 5
#define B_GROUPS     (NUM_BINS/256)               // 1024
#define B_BLOCKS     (B_GROUPS*9)                 // 9216 (8 splat + 1 fill per group)
#define TR_BLOCKS    ((PLANE/4)/256)              // 2048

__device__ int    g_count[NUM_BINS];
__device__ __align__(16)  float4 g_pts[NUM_BINS * STORE_CAP]; // (x,y,z,(idx<<3)|t)
__device__ __align__(128) float  g_scr[TT * PLANE];           // [t][x][y][z]

// ---- vector reductions ------------------------------------------------------
__device__ __forceinline__ void red4(float* p, float a, float b, float c, float d) {
    asm volatile("red.global.add.v4.f32 [%0], {%1,%2,%3,%4};"
                 :: "l"(p), "f"(a), "f"(b), "f"(c), "f"(d) : "memory");
}
__device__ __forceinline__ void red2(float* p, float a, float b) {
    asm volatile("red.global.add.v2.f32 [%0], {%1,%2};"
                 :: "l"(p), "f"(a), "f"(b) : "memory");
}

// ---- scalar bounds-checked splat (boundary + overflow path) ----------------
__device__ __forceinline__ void splat_scalar(float px, float py, float pz, int t)
{
    int cx = (int)floorf(px * 4.0f);
    int cy = (int)floorf(py * 4.0f);
    int cz = (int)floorf(pz * 4.0f);

    const float inv = 1.0f / (2.0f * 0.3f * 0.3f);
    float ex[3], ey[3], ez[3];
    #pragma unroll
    for (int o = 0; o < 3; o++) {
        float vx = px - ((float)(cx + o - 1) + 0.5f) * 0.25f;
        float vy = py - ((float)(cy + o - 1) + 0.5f) * 0.25f;
        float vz = pz - ((float)(cz + o - 1) + 0.5f) * 0.25f;
        ex[o] = __expf(-vx * vx * inv);
        ey[o] = __expf(-vy * vy * inv);
        ez[o] = __expf(-vz * vz * inv);
    }
    float* pl = g_scr + (size_t)t * PLANE;
    #pragma unroll
    for (int ix = 0; ix < 3; ix++) {
        int x = cx + ix - 1;
        if ((unsigned)x >= (unsigned)LL) continue;
        #pragma unroll
        for (int iy = 0; iy < 3; iy++) {
            int y = cy + iy - 1;
            if ((unsigned)y >= (unsigned)LL) continue;
            float exy = ex[ix] * ey[iy];
            #pragma unroll
            for (int iz = 0; iz < 3; iz++) {
                int z = cz + iz - 1;
                if ((unsigned)z >= (unsigned)LL) continue;
                atomicAdd(pl + x * XSLICE + y * LL + z, exy * ez[iz]);
            }
        }
    }
}

// ---------------------------------------------------------------------------
// Kernel A: interleaved [zero g_scr | bin scatter] (groups of 5 blocks).
// Zero stores double as an L2 prefetch of the scratch for the splat.
// ---------------------------------------------------------------------------
__global__ void __launch_bounds__(256)
zero_bin_kernel(const float* __restrict__ pts,
                const int* __restrict__ mask,
                const int* __restrict__ types)
{
    int g = blockIdx.x;
    int k = g / 5;
    int r = g - k * 5;

    if (r != 0) {
        int zid = (k * 4 + (r - 1)) * 256 + threadIdx.x;
        ((float4*)g_scr)[zid] = make_float4(0.f, 0.f, 0.f, 0.f);
        return;
    }

    int i = k * 256 + threadIdx.x;
    if (i >= N_POINTS) return;
    if (!mask[i]) return;

    float px = pts[3*i + 0];
    float py = pts[3*i + 1];
    float pz = pts[3*i + 2];
    int   t  = types[i];

    int bx = min(max((int)floorf(px * 2.0f), 0), DD - 1);
    int by = min(max((int)floorf(py * 2.0f), 0), DD - 1);
    int bz = min(max((int)floorf(pz * 2.0f), 0), DD - 1);
    int bin = (bx * DD + by) * DD + bz;
    int pos = atomicAdd(&g_count[bin], 1);
    if (pos < STORE_CAP) {
        g_pts[bin * STORE_CAP + pos] =
            make_float4(px, py, pz, __int_as_float((i << 3) | t));
    } else {
        splat_scalar(px, py, pz, t);   // P ~ 1e-22
    }
}

// ---------------------------------------------------------------------------
// splat work for one block (bin = tid/8, slot = tid%8) — R5 minimal-element
// vector-RED scheme (avg 31.5 RED elements / point).
// ---------------------------------------------------------------------------
__device__ __forceinline__ void do_splat(int sblock)
{
    int tid = sblock * 256 + threadIdx.x;
    int bin  = tid >> 3;
    int slot = tid & 7;

    int m = min(g_count[bin], STORE_CAP);
    for (int s = slot; s < m; s += 8) {
        float4 r = g_pts[bin * STORE_CAP + s];
        float px = r.x, py = r.y, pz = r.z;
        int t = __float_as_int(r.w) & 7;

        int cx = (int)floorf(px * 4.0f);
        int cy = (int)floorf(py * 4.0f);
        int cz = (int)floorf(pz * 4.0f);

        bool interior = ((unsigned)(cx - 1) < (unsigned)(LL - 2)) &&
                        ((unsigned)(cy - 1) < (unsigned)(LL - 2)) &&
                        ((unsigned)(cz - 1) < (unsigned)(LL - 2));
        if (!interior) { splat_scalar(px, py, pz, t); continue; }

        const float inv = 1.0f / (2.0f * 0.3f * 0.3f);
        float ex[3], ey[3], ez[3];
        #pragma unroll
        for (int o = 0; o < 3; o++) {
            float vx = px - ((float)(cx + o - 1) + 0.5f) * 0.25f;
            float vy = py - ((float)(cy + o - 1) + 0.5f) * 0.25f;
            float vz = pz - ((float)(cz + o - 1) + 0.5f) * 0.25f;
            ex[o] = __expf(-vx * vx * inv);
            ey[o] = __expf(-vy * vy * inv);
            ez[o] = __expf(-vz * vz * inv);
        }

        int zb = cz - 1;
        int a  = zb & 3;
        float* p00 = g_scr + (size_t)t * PLANE
                   + (cx - 1) * XSLICE + (cy - 1) * LL + zb;

        if (a == 0) {
            #pragma unroll
            for (int ix = 0; ix < 3; ix++)
                #pragma unroll
                for (int iy = 0; iy < 3; iy++) {
                    float w = ex[ix] * ey[iy];
                    float* p = p00 + ix * XSLICE + iy * LL;
                    red4(p, w*ez[0], w*ez[1], w*ez[2], 0.0f);
                }
        } else if (a == 1) {
            #pragma unroll
            for (int ix = 0; ix < 3; ix++)
                #pragma unroll
                for (int iy = 0; iy < 3; iy++) {
                    float w = ex[ix] * ey[iy];
                    float* p = p00 + ix * XSLICE + iy * LL;
                    red4(p - 1, 0.0f, w*ez[0], w*ez[1], w*ez[2]);
                }
        } else if (a == 2) {
            #pragma unroll
            for (int ix = 0; ix < 3; ix++)
                #pragma unroll
                for (int iy = 0; iy < 3; iy++) {
                    float w = ex[ix] * ey[iy];
                    float* p = p00 + ix * XSLICE + iy * LL;
                    red2(p, w*ez[0], w*ez[1]);
                    atomicAdd(p + 2, w*ez[2]);
                }
        } else {
            #pragma unroll
            for (int ix = 0; ix < 3; ix++)
                #pragma unroll
                for (int iy = 0; iy < 3; iy++) {
                    float w = ex[ix] * ey[iy];
                    float* p = p00 + ix * XSLICE + iy * LL;
                    atomicAdd(p, w*ez[0]);
                    red2(p + 1, w*ez[1], w*ez[2]);
                }
        }
    }
}

// ---------------------------------------------------------------------------
// fill work for one block (one bin per thread).
// ---------------------------------------------------------------------------
__device__ __forceinline__ void do_fill(int fb,
                                        float* __restrict__ buf,
                                        float* __restrict__ bmask)
{
    int b = fb * 256 + threadIdx.x;

    const float4* rec = &g_pts[(size_t)b * STORE_CAP];

    float w8[CAP];
    #pragma unroll
    for (int e = 0; e < CAP; e++) w8[e] = rec[e].w;

    int cnt = g_count[b];
    int m = min(cnt, STORE_CAP);

    int key[CAP];
    #pragma unroll
    for (int s = 0; s < CAP; s++) key[s] = 0x7FFFFFFF;

    #pragma unroll
    for (int e = 0; e < CAP; e++) {
        if (e >= m) break;
        int k = (__float_as_int(w8[e]) << 5) | e;
        #pragma unroll
        for (int j = 0; j < CAP; j++) {
            int lo = min(k, key[j]);
            int hi = max(k, key[j]);
            key[j] = lo;
            k = hi;
        }
    }
    for (int e = CAP; e < m; e++) {
        int k = (__float_as_int(rec[e].w) << 5) | e;
        #pragma unroll
        for (int j = 0; j < CAP; j++) {
            int lo = min(k, key[j]);
            int hi = max(k, key[j]);
            key[j] = lo;
            k = hi;
        }
    }

    int nval = min(cnt, CAP);
    float o[CAP * 3];
    float mk[CAP];
    #pragma unroll
    for (int s = 0; s < CAP; s++) {
        float x = 0.f, y = 0.f, z = 0.f, mv = 0.f;
        if (s < nval) {
            float4 r = rec[key[s] & (STORE_CAP - 1)];
            x = r.x; y = r.y; z = r.z; mv = 1.0f;
        }
        o[3*s + 0] = x; o[3*s + 1] = y; o[3*s + 2] = z;
        mk[s] = mv;
    }

    float4* bp = (float4*)(buf + (size_t)b * (CAP * 3));
    #pragma unroll
    for (int q = 0; q < 6; q++)
        bp[q] = make_float4(o[4*q + 0], o[4*q + 1], o[4*q + 2], o[4*q + 3]);

    float4* mp = (float4*)(bmask + (size_t)b * CAP);
    mp[0] = make_float4(mk[0], mk[1], mk[2], mk[3]);
    mp[1] = make_float4(mk[4], mk[5], mk[6], mk[7]);
}

// ---------------------------------------------------------------------------
// Kernel B: interleaved [splat | fill]. Groups of 9: r<8 splat, r==8 fill.
// ---------------------------------------------------------------------------
__global__ void __launch_bounds__(256)
splat_fill_kernel(float* __restrict__ buf, float* __restrict__ bmask)
{
    int g = blockIdx.x;
    int k = g / 9;
    int r = g - k * 9;
    if (r < 8) do_splat(k * 8 + r);
    else       do_fill(k, buf, bmask);
}

// ---------------------------------------------------------------------------
// Kernel C: transpose [t][x][y][z] -> [x][y][z][t] (quad version, no cleaning).
// ---------------------------------------------------------------------------
__global__ void __launch_bounds__(256)
transpose_kernel(float* __restrict__ lat)
{
    int idx = blockIdx.x * blockDim.x + threadIdx.x;  // [0, PLANE/4)
    int x   = idx >> 12;
    int rem = idx & 4095;
    int y   = rem >> 5;
    int z4  = (rem & 31) * 4;

    float4 v[TT];
    size_t base = (size_t)x * XSLICE + y * LL + z4;
    #pragma unroll
    for (int t = 0; t < TT; t++)
        v[t] = *(const float4*)(g_scr + (size_t)t * PLANE + base);

    float4* o = (float4*)(lat + base * TT);
    o[0] = make_float4(v[0].x, v[1].x, v[2].x, v[3].x);
    o[1] = make_float4(v[4].x, v[5].x, v[6].x, v[7].x);
    o[2] = make_float4(v[0].y, v[1].y, v[2].y, v[3].y);
    o[3] = make_float4(v[4].y, v[5].y, v[6].y, v[7].y);
    o[4] = make_float4(v[0].z, v[1].z, v[2].z, v[3].z);
    o[5] = make_float4(v[4].z, v[5].z, v[6].z, v[7].z);
    o[6] = make_float4(v[0].w, v[1].w, v[2].w, v[3].w);
    o[7] = make_float4(v[4].w, v[5].w, v[6].w, v[7].w);
}

// ---------------------------------------------------------------------------
extern "C" void kernel_launch(void* const* d_in, const int* in_sizes, int n_in,
                              void* d_out, int out_size)
{
    const float* points = (const float*)d_in[0];
    const int*   mask   = (const int*)d_in[1];
    const int*   types  = (const int*)d_in[2];

    float* out   = (float*)d_out;
    float* lat   = out;                       // [128,128,128,8]
    float* buf   = out + LAT_ELEMS;           // [262144,8,3]
    float* bmask = buf + BUF_ELEMS;           // [262144,8]

    void* cptr = nullptr;
    cudaGetSymbolAddress(&cptr, g_count);
    cudaMemsetAsync(cptr, 0, (size_t)NUM_BINS * sizeof(int), 0);

    zero_bin_kernel<<<A_BLOCKS, 256>>>(points, mask, types);
    splat_fill_kernel<<<B_BLOCKS, 256>>>(buf, bmask);
    transpose_kernel<<<TR_BLOCKS, 256>>>(lat);
}

// round 11
// speedup vs baseline: 1.9592x; 1.0796x over previous
#include <cuda_runtime.h>
#include <cuda_bf16.h>
#include <stdint.h>

#define N_POINTS  1048576
#define DD        64
#define NUM_BINS  (DD*DD*DD)         // 262144
#define LL        128
#define TT        8
#define CAP       8
#define STORE_CAP 32

#define LAT_ELEMS  (LL*LL*LL*TT)     // 16777216
#define BUF_ELEMS  (NUM_BINS*CAP*3)
#define PLANE      (LL*LL*LL)        // 2097152 floats per type-plane
#define XSLICE     (LL*LL)           // 16384

// grids
#define BIN_BLOCKS   (N_POINTS/4/256)             // 1024 (4 points/thread)
#define ZERO_BLOCKS  ((TT*PLANE/4)/256)           // 16384 (float4 stores)
#define A_BLOCKS     (BIN_BLOCKS*17)              // groups of 17: 1 bin + 16 zero
#define SPLAT_BLOCKS (NUM_BINS*4/256)             // 4096 (4 slots/bin)
#define B_GROUPS     (NUM_BINS/256)               // 1024
#define B_BLOCKS     (B_GROUPS*5)                 // 5120 (4 splat + 1 fill per group)
#define TR_BLOCKS    (PLANE/256)                  // 8192

__device__ int    g_count[NUM_BINS];
__device__ __align__(16)  float4 g_pts[NUM_BINS * STORE_CAP]; // (x,y,z,(idx<<3)|t)
__device__ __align__(128) float  g_scr[TT * PLANE];           // [t][x][y][z]

// ---- vector reduction ------------------------------------------------------
__device__ __forceinline__ void red4(float* p, float a, float b, float c, float d) {
    asm volatile("red.global.add.v4.f32 [%0], {%1,%2,%3,%4};"
                 :: "l"(p), "f"(a), "f"(b), "f"(c), "f"(d) : "memory");
}

// ---- scalar bounds-checked splat (boundary + overflow path) ----------------
__device__ __forceinline__ void splat_scalar(float px, float py, float pz, int t)
{
    int cx = (int)floorf(px * 4.0f);
    int cy = (int)floorf(py * 4.0f);
    int cz = (int)floorf(pz * 4.0f);

    const float inv = 1.0f / (2.0f * 0.3f * 0.3f);
    float ex[3], ey[3], ez[3];
    #pragma unroll
    for (int o = 0; o < 3; o++) {
        float vx = px - ((float)(cx + o - 1) + 0.5f) * 0.25f;
        float vy = py - ((float)(cy + o - 1) + 0.5f) * 0.25f;
        float vz = pz - ((float)(cz + o - 1) + 0.5f) * 0.25f;
        ex[o] = __expf(-vx * vx * inv);
        ey[o] = __expf(-vy * vy * inv);
        ez[o] = __expf(-vz * vz * inv);
    }
    float* pl = g_scr + (size_t)t * PLANE;
    #pragma unroll
    for (int ix = 0; ix < 3; ix++) {
        int x = cx + ix - 1;
        if ((unsigned)x >= (unsigned)LL) continue;
        #pragma unroll
        for (int iy = 0; iy < 3; iy++) {
            int y = cy + iy - 1;
            if ((unsigned)y >= (unsigned)LL) continue;
            float exy = ex[ix] * ey[iy];
            #pragma unroll
            for (int iz = 0; iz < 3; iz++) {
                int z = cz + iz - 1;
                if ((unsigned)z >= (unsigned)LL) continue;
                atomicAdd(pl + x * XSLICE + y * LL + z, exy * ez[iz]);
            }
        }
    }
}

// ---- bin one point ----------------------------------------------------------
__device__ __forceinline__ void bin_point(float px, float py, float pz,
                                          int mk, int t, int i)
{
    if (!mk) return;
    int bx = min(max((int)floorf(px * 2.0f), 0), DD - 1);
    int by = min(max((int)floorf(py * 2.0f), 0), DD - 1);
    int bz = min(max((int)floorf(pz * 2.0f), 0), DD - 1);
    int bin = (bx * DD + by) * DD + bz;
    int pos = atomicAdd(&g_count[bin], 1);
    if (pos < STORE_CAP) {
        g_pts[bin * STORE_CAP + pos] =
            make_float4(px, py, pz, __int_as_float((i << 3) | t));
    } else {
        splat_scalar(px, py, pz, t);   // P ~ 1e-22, keeps result exact
    }
}

// ---------------------------------------------------------------------------
// Kernel A: interleaved [zero g_scr | bin scatter], groups of 17 blocks.
// Zero stores double as an L2 prefetch of the scratch for the splat.
// Bin blocks handle 4 points/thread with vectorized loads (MLP).
// ---------------------------------------------------------------------------
__global__ void __launch_bounds__(256)
zero_bin_kernel(const float* __restrict__ pts,
                const int* __restrict__ mask,
                const int* __restrict__ types)
{
    int g = blockIdx.x;
    int k = g / 17;
    int r = g - k * 17;

    if (r != 0) {
        int zid = (k * 16 + (r - 1)) * 256 + threadIdx.x;
        ((float4*)g_scr)[zid] = make_float4(0.f, 0.f, 0.f, 0.f);
        return;
    }

    int q = k * 256 + threadIdx.x;       // quad index [0, N/4)
    int base = q * 4;

    const float4* p4 = (const float4*)(pts + 3 * (size_t)base);
    float4 a = p4[0];
    float4 b = p4[1];
    float4 c = p4[2];
    int4 mk = ((const int4*)mask)[q];
    int4 ty = ((const int4*)types)[q];

    bin_point(a.x, a.y, a.z, mk.x, ty.x, base + 0);
    bin_point(a.w, b.x, b.y, mk.y, ty.y, base + 1);
    bin_point(b.z, b.w, c.x, mk.z, ty.z, base + 2);
    bin_point(c.y, c.z, c.w, mk.w, ty.w, base + 3);
}

// ---------------------------------------------------------------------------
// splat work for one block (bin = tid/4, slot = tid%4) — shifted-u8 two-red4
// scheme (uniform first red4, predicated second; 2 divergence paths max).
// ---------------------------------------------------------------------------
__device__ __forceinline__ void do_splat(int sblock)
{
    int tid = sblock * 256 + threadIdx.x;
    int bin  = tid >> 2;
    int slot = tid & 3;

    int m = min(g_count[bin], STORE_CAP);
    for (int s = slot; s < m; s += 4) {
        float4 r = g_pts[bin * STORE_CAP + s];
        float px = r.x, py = r.y, pz = r.z;
        int t = __float_as_int(r.w) & 7;

        int cx = (int)floorf(px * 4.0f);
        int cy = (int)floorf(py * 4.0f);
        int cz = (int)floorf(pz * 4.0f);

        bool interior = ((unsigned)(cx - 1) < (unsigned)(LL - 2)) &&
                        ((unsigned)(cy - 1) < (unsigned)(LL - 2)) &&
                        ((unsigned)(cz - 1) < (unsigned)(LL - 2));
        if (!interior) { splat_scalar(px, py, pz, t); continue; }

        const float inv = 1.0f / (2.0f * 0.3f * 0.3f);
        float ex[3], ey[3], ez[3];
        #pragma unroll
        for (int o = 0; o < 3; o++) {
            float vx = px - ((float)(cx + o - 1) + 0.5f) * 0.25f;
            float vy = py - ((float)(cy + o - 1) + 0.5f) * 0.25f;
            float vz = pz - ((float)(cz + o - 1) + 0.5f) * 0.25f;
            ex[o] = __expf(-vx * vx * inv);
            ey[o] = __expf(-vy * vy * inv);
            ez[o] = __expf(-vz * vz * inv);
        }

        int zb = cz - 1;
        int a  = zb & 3;

        // shifted ez pattern: u[a..a+2] = ez[0..2], zeros elsewhere
        float u[8];
        #pragma unroll
        for (int q = 0; q < 8; q++) {
            int d = q - a;
            u[q] = (d == 0) ? ez[0] : (d == 1) ? ez[1] : (d == 2) ? ez[2] : 0.0f;
        }
        bool two = (a >= 2);

        float* q0 = g_scr + (size_t)t * PLANE
                  + (cx - 1) * XSLICE + (cy - 1) * LL + (zb - a);

        #pragma unroll
        for (int ix = 0; ix < 3; ix++) {
            #pragma unroll
            for (int iy = 0; iy < 3; iy++) {
                float w = ex[ix] * ey[iy];
                float* p = q0 + ix * XSLICE + iy * LL;
                red4(p, w*u[0], w*u[1], w*u[2], w*u[3]);
                if (two)
                    red4(p + 4, w*u[4], w*u[5], w*u[6], w*u[7]);
            }
        }
    }
}

// ---------------------------------------------------------------------------
// fill work for one block (one bin per thread).
// ---------------------------------------------------------------------------
__device__ __forceinline__ void do_fill(int fb,
                                        float* __restrict__ buf,
                                        float* __restrict__ bmask)
{
    int b = fb * 256 + threadIdx.x;

    const float4* rec = &g_pts[(size_t)b * STORE_CAP];

    float w8[CAP];
    #pragma unroll
    for (int e = 0; e < CAP; e++) w8[e] = rec[e].w;

    int cnt = g_count[b];
    int m = min(cnt, STORE_CAP);

    int key[CAP];
    #pragma unroll
    for (int s = 0; s < CAP; s++) key[s] = 0x7FFFFFFF;

    #pragma unroll
    for (int e = 0; e < CAP; e++) {
        if (e >= m) break;
        int k = (__float_as_int(w8[e]) << 5) | e;
        #pragma unroll
        for (int j = 0; j < CAP; j++) {
            int lo = min(k, key[j]);
            int hi = max(k, key[j]);
            key[j] = lo;
            k = hi;
        }
    }
    for (int e = CAP; e < m; e++) {
        int k = (__float_as_int(rec[e].w) << 5) | e;
        #pragma unroll
        for (int j = 0; j < CAP; j++) {
            int lo = min(k, key[j]);
            int hi = max(k, key[j]);
            key[j] = lo;
            k = hi;
        }
    }

    int nval = min(cnt, CAP);
    float o[CAP * 3];
    float mk[CAP];
    #pragma unroll
    for (int s = 0; s < CAP; s++) {
        float x = 0.f, y = 0.f, z = 0.f, mv = 0.f;
        if (s < nval) {
            float4 r = rec[key[s] & (STORE_CAP - 1)];
            x = r.x; y = r.y; z = r.z; mv = 1.0f;
        }
        o[3*s + 0] = x; o[3*s + 1] = y; o[3*s + 2] = z;
        mk[s] = mv;
    }

    float4* bp = (float4*)(buf + (size_t)b * (CAP * 3));
    #pragma unroll
    for (int q = 0; q < 6; q++)
        bp[q] = make_float4(o[4*q + 0], o[4*q + 1], o[4*q + 2], o[4*q + 3]);

    float4* mp = (float4*)(bmask + (size_t)b * CAP);
    mp[0] = make_float4(mk[0], mk[1], mk[2], mk[3]);
    mp[1] = make_float4(mk[4], mk[5], mk[6], mk[7]);
}

// ---------------------------------------------------------------------------
// Kernel B: interleaved [splat | fill]. Groups of 5: r<4 splat, r==4 fill.
// ---------------------------------------------------------------------------
__global__ void __launch_bounds__(256)
splat_fill_kernel(float* __restrict__ buf, float* __restrict__ bmask)
{
    int g = blockIdx.x;
    int k = g / 5;
    int r = g - k * 5;
    if (r < 4) do_splat(k * 4 + r);
    else       do_fill(k, buf, bmask);
}

// ---------------------------------------------------------------------------
// Kernel C: transpose scratch [t][x][y][z] -> lattice [x][y][z][t].
// ---------------------------------------------------------------------------
__global__ void __launch_bounds__(256)
transpose_kernel(float* __restrict__ lat)
{
    int v = blockIdx.x * blockDim.x + threadIdx.x;   // (x*128+y)*128+z
    if (v >= PLANE) return;

    float o[TT];
    #pragma unroll
    for (int t = 0; t < TT; t++)
        o[t] = g_scr[(size_t)t * PLANE + v];

    float4* out = (float4*)(lat + (size_t)v * TT);
    out[0] = make_float4(o[0], o[1], o[2], o[3]);
    out[1] = make_float4(o[4], o[5], o[6], o[7]);
}

// ---------------------------------------------------------------------------
extern "C" void kernel_launch(void* const* d_in, const int* in_sizes, int n_in,
                              void* d_out, int out_size)
{
    const float* points = (const float*)d_in[0];
    const int*   mask   = (const int*)d_in[1];
    const int*   types  = (const int*)d_in[2];

    float* out   = (float*)d_out;
    float* lat   = out;                       // [128,128,128,8]
    float* buf   = out + LAT_ELEMS;           // [262144,8,3]
    float* bmask = buf + BUF_ELEMS;           // [262144,8]

    void* cptr = nullptr;
    cudaGetSymbolAddress(&cptr, g_count);
    cudaMemsetAsync(cptr, 0, (size_t)NUM_BINS * sizeof(int), 0);

    zero_bin_kernel<<<A_BLOCKS, 256>>>(points, mask, types);
    splat_fill_kernel<<<B_BLOCKS, 256>>>(buf, bmask);
    transpose_kernel<<<TR_BLOCKS, 256>>>(lat);
}